// round 1
// baseline (speedup 1.0000x reference)
#include <cuda_runtime.h>
#include <cuda_bf16.h>

#define MAX_N 50000
#define MAX_E 600000
#define D 128

// scratch (no allocation allowed -> __device__ globals)
__device__ float g_h1[MAX_N * D];
__device__ float g_agg1[MAX_N * D];
__device__ float g_h2[MAX_N * D];
__device__ float g_deg[MAX_N];
__device__ float g_dis[MAX_N];
__device__ float g_norm[MAX_E];

// ---------------- degree / norm ----------------
__global__ void deg_kernel(const float* __restrict__ w, const int* __restrict__ row, int E) {
    int e = blockIdx.x * blockDim.x + threadIdx.x;
    if (e < E) atomicAdd(&g_deg[row[e]], w[e]);
}

__global__ void dis_kernel(int n) {
    int i = blockIdx.x * blockDim.x + threadIdx.x;
    if (i < n) g_dis[i] = rsqrtf(g_deg[i]);
}

__global__ void norm_kernel(const float* __restrict__ w, const int* __restrict__ row,
                            const int* __restrict__ col, int E) {
    int e = blockIdx.x * blockDim.x + threadIdx.x;
    if (e < E) g_norm[e] = g_dis[row[e]] * w[e] * g_dis[col[e]];
}

// ---------------- GEMM: out = X @ W^T + b  (optionally relu(X) on input) ----------------
// block = 256 threads, 32 rows per block, 4x4 register tile per thread.
// smem: Wt[128][132] (Wt[k][c] = W[c][k]) + xsT[128][36] (xsT[k][r] = X[row0+r][k])
#define WT_STRIDE 132
#define XT_STRIDE 36
#define GEMM_SMEM ((D * WT_STRIDE + D * XT_STRIDE) * 4)

template <bool RELU_IN>
__global__ void gemm_kernel(const float* __restrict__ X, const float* __restrict__ W,
                            const float* __restrict__ bias, float* __restrict__ out, int n) {
    extern __shared__ float smem[];
    float* Wt  = smem;                  // D * WT_STRIDE
    float* xsT = smem + D * WT_STRIDE;  // D * XT_STRIDE

    int tid = threadIdx.x;
    // load W transposed (coalesced global reads)
    for (int i = tid; i < D * D; i += 256) {
        int c = i >> 7, k = i & 127;
        Wt[k * WT_STRIDE + c] = W[i];
    }
    int row0 = blockIdx.x * 32;
    // load 32 input rows, transposed
    for (int i = tid; i < 32 * D; i += 256) {
        int r = i >> 7, k = i & 127;
        int gr = row0 + r;
        float v = (gr < n) ? X[(size_t)gr * D + k] : 0.f;
        if (RELU_IN) v = fmaxf(v, 0.f);
        xsT[k * XT_STRIDE + r] = v;
    }
    __syncthreads();

    int tx = tid & 31;   // col group: cols 4*tx .. 4*tx+3
    int ty = tid >> 5;   // row group: rows row0 + 4*ty .. +3
    float acc[4][4];
    #pragma unroll
    for (int i = 0; i < 4; i++)
        #pragma unroll
        for (int j = 0; j < 4; j++) acc[i][j] = 0.f;

    #pragma unroll 4
    for (int k = 0; k < D; k++) {
        float4 a = *(const float4*)&xsT[k * XT_STRIDE + 4 * ty];  // broadcast within warp
        float4 b = *(const float4*)&Wt[k * WT_STRIDE + 4 * tx];   // conflict-free
        acc[0][0] += a.x * b.x; acc[0][1] += a.x * b.y; acc[0][2] += a.x * b.z; acc[0][3] += a.x * b.w;
        acc[1][0] += a.y * b.x; acc[1][1] += a.y * b.y; acc[1][2] += a.y * b.z; acc[1][3] += a.y * b.w;
        acc[2][0] += a.z * b.x; acc[2][1] += a.z * b.y; acc[2][2] += a.z * b.z; acc[2][3] += a.z * b.w;
        acc[3][0] += a.w * b.x; acc[3][1] += a.w * b.y; acc[3][2] += a.w * b.z; acc[3][3] += a.w * b.w;
    }

    float4 bb = *(const float4*)&bias[4 * tx];
    #pragma unroll
    for (int i = 0; i < 4; i++) {
        int gr = row0 + 4 * ty + i;
        if (gr < n) {
            float4 o;
            o.x = acc[i][0] + bb.x;
            o.y = acc[i][1] + bb.y;
            o.z = acc[i][2] + bb.z;
            o.w = acc[i][3] + bb.w;
            *(float4*)&out[(size_t)gr * D + 4 * tx] = o;
        }
    }
}

// ---------------- scatter: agg[col] += norm[e] * h[row]  (warp per edge) ----------------
__global__ void scatter_kernel(const float4* __restrict__ h, float* __restrict__ out,
                               const int* __restrict__ row, const int* __restrict__ col, int E) {
    int g = blockIdx.x * blockDim.x + threadIdx.x;
    int e = g >> 5;
    int lane = g & 31;
    if (e >= E) return;
    int r = row[e];
    int c = col[e];
    float nm = g_norm[e];
    float4 v = h[(size_t)r * 32 + lane];  // 128 floats/row = 32 float4
    float* dst = out + (size_t)c * D + lane * 4;
    atomicAdd(dst + 0, nm * v.x);
    atomicAdd(dst + 1, nm * v.y);
    atomicAdd(dst + 2, nm * v.z);
    atomicAdd(dst + 3, nm * v.w);
}

extern "C" void kernel_launch(void* const* d_in, const int* in_sizes, int n_in,
                              void* d_out, int out_size) {
    const float* x  = (const float*)d_in[0];
    const int*   ei = (const int*)d_in[1];
    const float* ew = (const float*)d_in[2];
    const float* W1 = (const float*)d_in[3];
    const float* b1 = (const float*)d_in[4];
    const float* W2 = (const float*)d_in[5];
    const float* b2 = (const float*)d_in[6];
    float* out = (float*)d_out;

    int n = in_sizes[0] / D;
    int E = in_sizes[2];
    const int* row = ei;
    const int* col = ei + E;

    void *p_h1, *p_agg1, *p_h2, *p_deg;
    cudaGetSymbolAddress(&p_h1, g_h1);
    cudaGetSymbolAddress(&p_agg1, g_agg1);
    cudaGetSymbolAddress(&p_h2, g_h2);
    cudaGetSymbolAddress(&p_deg, g_deg);

    cudaFuncSetAttribute(gemm_kernel<false>, cudaFuncAttributeMaxDynamicSharedMemorySize, GEMM_SMEM);
    cudaFuncSetAttribute(gemm_kernel<true>,  cudaFuncAttributeMaxDynamicSharedMemorySize, GEMM_SMEM);

    // normalization (shared by both layers)
    cudaMemsetAsync(p_deg, 0, (size_t)n * sizeof(float));
    deg_kernel<<<(E + 255) / 256, 256>>>(ew, row, E);
    dis_kernel<<<(n + 255) / 256, 256>>>(n);
    norm_kernel<<<(E + 255) / 256, 256>>>(ew, row, col, E);

    int gemm_blocks = (n + 31) / 32;
    long long scatter_threads = (long long)E * 32;
    int scatter_blocks = (int)((scatter_threads + 255) / 256);

    // layer 1
    gemm_kernel<false><<<gemm_blocks, 256, GEMM_SMEM>>>(x, W1, b1, (float*)p_h1, n);
    cudaMemsetAsync(p_agg1, 0, (size_t)n * D * sizeof(float));
    scatter_kernel<<<scatter_blocks, 256>>>((const float4*)p_h1, (float*)p_agg1, row, col, E);

    // layer 2 (relu fused into GEMM input load)
    gemm_kernel<true><<<gemm_blocks, 256, GEMM_SMEM>>>((const float*)p_agg1, W2, b2, (float*)p_h2, n);
    cudaMemsetAsync(out, 0, (size_t)out_size * sizeof(float));
    scatter_kernel<<<scatter_blocks, 256>>>((const float4*)p_h2, out, row, col, E);
}

// round 2
// speedup vs baseline: 2.0230x; 2.0230x over previous
#include <cuda_runtime.h>
#include <cuda_bf16.h>

#define MAX_N 50000
#define MAX_E 600000
#define D 128

// scratch (no allocation allowed -> __device__ globals)
__device__ float g_h1[MAX_N * D];
__device__ float g_agg1[MAX_N * D];
__device__ float g_h2[MAX_N * D];
__device__ float g_deg[MAX_N];
__device__ float g_dis[MAX_N];
__device__ float g_norm[MAX_E];

// ---------------- f32x2 packed helpers (sm_103a) ----------------
__device__ __forceinline__ unsigned long long ffma2(unsigned long long a,
                                                    unsigned long long b,
                                                    unsigned long long c) {
    unsigned long long d;
    asm("fma.rn.f32x2 %0, %1, %2, %3;" : "=l"(d) : "l"(a), "l"(b), "l"(c));
    return d;
}
__device__ __forceinline__ unsigned long long pack2(float x, float y) {
    unsigned long long r;
    asm("mov.b64 %0, {%1, %2};" : "=l"(r) : "f"(x), "f"(y));
    return r;
}
__device__ __forceinline__ float2 unpack2(unsigned long long v) {
    float2 f;
    asm("mov.b64 {%0, %1}, %2;" : "=f"(f.x), "=f"(f.y) : "l"(v));
    return f;
}

// ---------------- degree / norm ----------------
__global__ void deg_kernel(const float* __restrict__ w, const int* __restrict__ row, int E) {
    int e = blockIdx.x * blockDim.x + threadIdx.x;
    if (e < E) atomicAdd(&g_deg[row[e]], w[e]);
}

__global__ void dis_kernel(int n) {
    int i = blockIdx.x * blockDim.x + threadIdx.x;
    if (i < n) g_dis[i] = rsqrtf(g_deg[i]);
}

__global__ void norm_kernel(const float* __restrict__ w, const int* __restrict__ row,
                            const int* __restrict__ col, int E) {
    int e = blockIdx.x * blockDim.x + threadIdx.x;
    if (e < E) g_norm[e] = g_dis[row[e]] * w[e] * g_dis[col[e]];
}

// ---------------- GEMM: out = X @ W^T + b  (optionally relu(X) on input) ----------------
// block = 256 threads, 64 rows per block, 8 rows x 4 cols per thread, f32x2 FMA.
// smem: Wt[128][132] (Wt[k][c] = W[c][k]) + xsT[128][72] (xsT[k][r] = X[row0+r][k])
#define WT_S 132
#define XT_S 72
#define GEMM_SMEM ((D * WT_S + D * XT_S) * 4)

template <bool RELU_IN>
__global__ void gemm_kernel(const float* __restrict__ X, const float* __restrict__ W,
                            const float* __restrict__ bias, float* __restrict__ out, int n) {
    extern __shared__ float smem[];
    float* Wt  = smem;             // D * WT_S
    float* xsT = smem + D * WT_S;  // D * XT_S

    int tid = threadIdx.x;
    // load W transposed (coalesced global reads, padded smem writes)
    for (int i = tid; i < D * D; i += 256) {
        int c = i >> 7, k = i & 127;
        Wt[k * WT_S + c] = W[i];
    }
    int row0 = blockIdx.x * 64;
    // load 64 input rows, transposed
    for (int i = tid; i < 64 * D; i += 256) {
        int r = i >> 7, k = i & 127;
        int gr = row0 + r;
        float v = (gr < n) ? X[(size_t)gr * D + k] : 0.f;
        if (RELU_IN) v = fmaxf(v, 0.f);
        xsT[k * XT_S + r] = v;
    }
    __syncthreads();

    int tx = tid & 31;   // cols 4*tx .. 4*tx+3
    int ty = tid >> 5;   // rows row0 + 8*ty .. +7  (4 packed row-pairs)
    unsigned long long acc[4][4];  // [rowpair][col]
    #pragma unroll
    for (int p = 0; p < 4; p++)
        #pragma unroll
        for (int j = 0; j < 4; j++) acc[p][j] = 0ull;

    const float* xbase = &xsT[8 * ty];
    const float* wbase = &Wt[4 * tx];

    #pragma unroll 4
    for (int k = 0; k < D; k++) {
        // 8 row values as 4 natural f32x2 pairs (consecutive rows)
        ulonglong2 a01 = *(const ulonglong2*)(xbase + k * XT_S);      // rows 0-3
        ulonglong2 a23 = *(const ulonglong2*)(xbase + k * XT_S + 4);  // rows 4-7
        float4 bv = *(const float4*)(wbase + k * WT_S);
        unsigned long long b0 = pack2(bv.x, bv.x);
        unsigned long long b1 = pack2(bv.y, bv.y);
        unsigned long long b2 = pack2(bv.z, bv.z);
        unsigned long long b3 = pack2(bv.w, bv.w);

        acc[0][0] = ffma2(a01.x, b0, acc[0][0]);
        acc[0][1] = ffma2(a01.x, b1, acc[0][1]);
        acc[0][2] = ffma2(a01.x, b2, acc[0][2]);
        acc[0][3] = ffma2(a01.x, b3, acc[0][3]);
        acc[1][0] = ffma2(a01.y, b0, acc[1][0]);
        acc[1][1] = ffma2(a01.y, b1, acc[1][1]);
        acc[1][2] = ffma2(a01.y, b2, acc[1][2]);
        acc[1][3] = ffma2(a01.y, b3, acc[1][3]);
        acc[2][0] = ffma2(a23.x, b0, acc[2][0]);
        acc[2][1] = ffma2(a23.x, b1, acc[2][1]);
        acc[2][2] = ffma2(a23.x, b2, acc[2][2]);
        acc[2][3] = ffma2(a23.x, b3, acc[2][3]);
        acc[3][0] = ffma2(a23.y, b0, acc[3][0]);
        acc[3][1] = ffma2(a23.y, b1, acc[3][1]);
        acc[3][2] = ffma2(a23.y, b2, acc[3][2]);
        acc[3][3] = ffma2(a23.y, b3, acc[3][3]);
    }

    float4 bb = *(const float4*)&bias[4 * tx];
    #pragma unroll
    for (int p = 0; p < 4; p++) {
        float2 c0 = unpack2(acc[p][0]);
        float2 c1 = unpack2(acc[p][1]);
        float2 c2 = unpack2(acc[p][2]);
        float2 c3 = unpack2(acc[p][3]);
        int gr0 = row0 + 8 * ty + 2 * p;
        if (gr0 < n) {
            float4 o = make_float4(c0.x + bb.x, c1.x + bb.y, c2.x + bb.z, c3.x + bb.w);
            *(float4*)&out[(size_t)gr0 * D + 4 * tx] = o;
        }
        if (gr0 + 1 < n) {
            float4 o = make_float4(c0.y + bb.x, c1.y + bb.y, c2.y + bb.z, c3.y + bb.w);
            *(float4*)&out[(size_t)(gr0 + 1) * D + 4 * tx] = o;
        }
    }
}

// ---------------- scatter: agg[col] += norm[e] * h[row]  (warp per edge, v4 red) ----------------
__global__ void scatter_kernel(const float4* __restrict__ h, float* __restrict__ out,
                               const int* __restrict__ row, const int* __restrict__ col, int E) {
    int g = blockIdx.x * blockDim.x + threadIdx.x;
    int e = g >> 5;
    int lane = g & 31;
    if (e >= E) return;
    int r = row[e];
    int c = col[e];
    float nm = g_norm[e];
    float4 v = h[(size_t)r * 32 + lane];  // 128 floats/row = 32 float4
    float* dst = out + (size_t)c * D + lane * 4;
    asm volatile("red.global.add.v4.f32 [%0], {%1, %2, %3, %4};"
                 :: "l"(dst), "f"(nm * v.x), "f"(nm * v.y), "f"(nm * v.z), "f"(nm * v.w)
                 : "memory");
}

extern "C" void kernel_launch(void* const* d_in, const int* in_sizes, int n_in,
                              void* d_out, int out_size) {
    const float* x  = (const float*)d_in[0];
    const int*   ei = (const int*)d_in[1];
    const float* ew = (const float*)d_in[2];
    const float* W1 = (const float*)d_in[3];
    const float* b1 = (const float*)d_in[4];
    const float* W2 = (const float*)d_in[5];
    const float* b2 = (const float*)d_in[6];
    float* out = (float*)d_out;

    int n = in_sizes[0] / D;
    int E = in_sizes[2];
    const int* row = ei;
    const int* col = ei + E;

    void *p_h1, *p_agg1, *p_h2, *p_deg;
    cudaGetSymbolAddress(&p_h1, g_h1);
    cudaGetSymbolAddress(&p_agg1, g_agg1);
    cudaGetSymbolAddress(&p_h2, g_h2);
    cudaGetSymbolAddress(&p_deg, g_deg);

    cudaFuncSetAttribute(gemm_kernel<false>, cudaFuncAttributeMaxDynamicSharedMemorySize, GEMM_SMEM);
    cudaFuncSetAttribute(gemm_kernel<true>,  cudaFuncAttributeMaxDynamicSharedMemorySize, GEMM_SMEM);

    // normalization (shared by both layers)
    cudaMemsetAsync(p_deg, 0, (size_t)n * sizeof(float));
    deg_kernel<<<(E + 255) / 256, 256>>>(ew, row, E);
    dis_kernel<<<(n + 255) / 256, 256>>>(n);
    norm_kernel<<<(E + 255) / 256, 256>>>(ew, row, col, E);

    int gemm_blocks = (n + 63) / 64;
    long long scatter_threads = (long long)E * 32;
    int scatter_blocks = (int)((scatter_threads + 255) / 256);

    // layer 1
    gemm_kernel<false><<<gemm_blocks, 256, GEMM_SMEM>>>(x, W1, b1, (float*)p_h1, n);
    cudaMemsetAsync(p_agg1, 0, (size_t)n * D * sizeof(float));
    scatter_kernel<<<scatter_blocks, 256>>>((const float4*)p_h1, (float*)p_agg1, row, col, E);

    // layer 2 (relu fused into GEMM input load)
    gemm_kernel<true><<<gemm_blocks, 256, GEMM_SMEM>>>((const float*)p_agg1, W2, b2, (float*)p_h2, n);
    cudaMemsetAsync(out, 0, (size_t)out_size * sizeof(float));
    scatter_kernel<<<scatter_blocks, 256>>>((const float4*)p_h2, out, row, col, E);
}

// round 4
// speedup vs baseline: 2.1968x; 1.0859x over previous
#include <cuda_runtime.h>
#include <cuda_bf16.h>

#define MAX_N 50000
#define MAX_E 600000
#define D 128

// scratch (no allocation allowed -> __device__ globals)
__device__ float g_h1[MAX_N * D];
__device__ float g_agg1[MAX_N * D];
__device__ float g_h2[MAX_N * D];
__device__ float g_deg[MAX_N];
__device__ float g_dis[MAX_N];
__device__ int   g_cnt[MAX_N];
__device__ int   g_cnt2[MAX_N];
__device__ int   g_rowptr[MAX_N + 1];
__device__ int2  g_edge[MAX_E];     // (src_row, norm bits) sorted by dst col
__device__ float g_Wt1[D * D];
__device__ float g_Wt2[D * D];

// ---------------- f32x2 packed helpers (sm_103a) ----------------
__device__ __forceinline__ unsigned long long ffma2(unsigned long long a,
                                                    unsigned long long b,
                                                    unsigned long long c) {
    unsigned long long d;
    asm("fma.rn.f32x2 %0, %1, %2, %3;" : "=l"(d) : "l"(a), "l"(b), "l"(c));
    return d;
}
__device__ __forceinline__ unsigned long long pack2(float x, float y) {
    unsigned long long r;
    asm("mov.b64 %0, {%1, %2};" : "=l"(r) : "f"(x), "f"(y));
    return r;
}
__device__ __forceinline__ float2 unpack2(unsigned long long v) {
    float2 f;
    asm("mov.b64 {%0, %1}, %2;" : "=f"(f.x), "=f"(f.y) : "l"(v));
    return f;
}

// ---------------- W transpose: Wt[k][c] = W[c][k] ----------------
__global__ void transpose_kernel(const float* __restrict__ A, float* __restrict__ At) {
    __shared__ float tile[32][33];
    int x = blockIdx.x * 32 + threadIdx.x;
    int y = blockIdx.y * 32 + threadIdx.y;
    #pragma unroll
    for (int i = 0; i < 32; i += 8)
        tile[threadIdx.y + i][threadIdx.x] = A[(y + i) * D + x];
    __syncthreads();
    x = blockIdx.y * 32 + threadIdx.x;
    y = blockIdx.x * 32 + threadIdx.y;
    #pragma unroll
    for (int i = 0; i < 32; i += 8)
        At[(y + i) * D + x] = tile[threadIdx.x][threadIdx.y + i];
}

// ---------------- CSR build ----------------
__global__ void hist_kernel(const float* __restrict__ w, const int* __restrict__ row,
                            const int* __restrict__ col, int E) {
    int e = blockIdx.x * blockDim.x + threadIdx.x;
    if (e < E) {
        atomicAdd(&g_deg[row[e]], w[e]);
        atomicAdd(&g_cnt[col[e]], 1);
    }
}

__global__ void dis_kernel(int n) {
    int i = blockIdx.x * blockDim.x + threadIdx.x;
    if (i < n) g_dis[i] = rsqrtf(g_deg[i]);
}

// single-block exclusive scan of g_cnt -> g_rowptr (double-buffered Hillis-Steele)
__global__ void scan_kernel(int n, int E) {
    __shared__ int sa[1024];
    __shared__ int sb[1024];
    int t = threadIdx.x;
    int C = (n + 1023) >> 10;
    int base = t * C;
    int s = 0;
    for (int i = 0; i < C; i++) {
        int idx = base + i;
        if (idx < n) s += g_cnt[idx];
    }
    sa[t] = s;
    __syncthreads();
    int* src = sa;
    int* dst = sb;
    for (int off = 1; off < 1024; off <<= 1) {
        int v = src[t];
        if (t >= off) v += src[t - off];
        dst[t] = v;
        __syncthreads();
        int* tmp = src; src = dst; dst = tmp;
    }
    int run = src[t] - s;  // exclusive offset for this chunk
    for (int i = 0; i < C; i++) {
        int idx = base + i;
        if (idx < n) {
            g_rowptr[idx] = run;
            run += g_cnt[idx];
        }
    }
    if (t == 0) g_rowptr[n] = E;
}

__global__ void fill_kernel(const float* __restrict__ w, const int* __restrict__ row,
                            const int* __restrict__ col, int E) {
    int e = blockIdx.x * blockDim.x + threadIdx.x;
    if (e < E) {
        int c = col[e];
        int r = row[e];
        int pos = atomicAdd(&g_cnt2[c], 1);
        float nm = g_dis[r] * w[e] * g_dis[c];
        g_edge[g_rowptr[c] + pos] = make_int2(r, __float_as_int(nm));
    }
}

// ---------------- GEMM: out = X @ W^T + b (Wt pre-transposed, read via L1) ----------------
// block = 256 threads, 64 rows per block, 8 rows x 4 cols per thread, f32x2 FMA.
#define XT_S 72

template <bool RELU_IN>
__global__ __launch_bounds__(256, 4) void gemm_kernel(const float* __restrict__ X,
                                                      const float* __restrict__ Wt,
                                                      const float* __restrict__ bias,
                                                      float* __restrict__ out, int n) {
    __shared__ float xsT[D * XT_S];  // 36.9 KB

    int tid = threadIdx.x;
    int row0 = blockIdx.x * 64;
    for (int i = tid; i < 64 * D; i += 256) {
        int r = i >> 7, k = i & 127;
        int gr = row0 + r;
        float v = (gr < n) ? X[(size_t)gr * D + k] : 0.f;
        if (RELU_IN) v = fmaxf(v, 0.f);
        xsT[k * XT_S + r] = v;
    }
    __syncthreads();

    int tx = tid & 31;   // cols 4*tx .. 4*tx+3
    int ty = tid >> 5;   // rows row0 + 8*ty .. +7 (4 packed row-pairs)
    unsigned long long acc[4][4];
    #pragma unroll
    for (int p = 0; p < 4; p++)
        #pragma unroll
        for (int j = 0; j < 4; j++) acc[p][j] = 0ull;

    const float* xbase = &xsT[8 * ty];
    const float4* wbase = (const float4*)(Wt) + tx;  // Wt[k*128 + 4*tx]

    #pragma unroll 4
    for (int k = 0; k < D; k++) {
        ulonglong2 a01 = *(const ulonglong2*)(xbase + k * XT_S);      // rows 0-3
        ulonglong2 a23 = *(const ulonglong2*)(xbase + k * XT_S + 4);  // rows 4-7
        float4 bv = __ldg(wbase + k * 32);
        unsigned long long b0 = pack2(bv.x, bv.x);
        unsigned long long b1 = pack2(bv.y, bv.y);
        unsigned long long b2 = pack2(bv.z, bv.z);
        unsigned long long b3 = pack2(bv.w, bv.w);

        acc[0][0] = ffma2(a01.x, b0, acc[0][0]);
        acc[0][1] = ffma2(a01.x, b1, acc[0][1]);
        acc[0][2] = ffma2(a01.x, b2, acc[0][2]);
        acc[0][3] = ffma2(a01.x, b3, acc[0][3]);
        acc[1][0] = ffma2(a01.y, b0, acc[1][0]);
        acc[1][1] = ffma2(a01.y, b1, acc[1][1]);
        acc[1][2] = ffma2(a01.y, b2, acc[1][2]);
        acc[1][3] = ffma2(a01.y, b3, acc[1][3]);
        acc[2][0] = ffma2(a23.x, b0, acc[2][0]);
        acc[2][1] = ffma2(a23.x, b1, acc[2][1]);
        acc[2][2] = ffma2(a23.x, b2, acc[2][2]);
        acc[2][3] = ffma2(a23.x, b3, acc[2][3]);
        acc[3][0] = ffma2(a23.y, b0, acc[3][0]);
        acc[3][1] = ffma2(a23.y, b1, acc[3][1]);
        acc[3][2] = ffma2(a23.y, b2, acc[3][2]);
        acc[3][3] = ffma2(a23.y, b3, acc[3][3]);
    }

    float4 bb = *(const float4*)&bias[4 * tx];
    #pragma unroll
    for (int p = 0; p < 4; p++) {
        float2 c0 = unpack2(acc[p][0]);
        float2 c1 = unpack2(acc[p][1]);
        float2 c2 = unpack2(acc[p][2]);
        float2 c3 = unpack2(acc[p][3]);
        int gr0 = row0 + 8 * ty + 2 * p;
        if (gr0 < n) {
            float4 o = make_float4(c0.x + bb.x, c1.x + bb.y, c2.x + bb.z, c3.x + bb.w);
            *(float4*)&out[(size_t)gr0 * D + 4 * tx] = o;
        }
        if (gr0 + 1 < n) {
            float4 o = make_float4(c0.y + bb.x, c1.y + bb.y, c2.y + bb.z, c3.y + bb.w);
            *(float4*)&out[(size_t)(gr0 + 1) * D + 4 * tx] = o;
        }
    }
}

// ---------------- gather: out[c] = sum_{e in CSR[c]} norm[e] * h[row[e]] ----------------
__global__ void gather_kernel(const float4* __restrict__ h, float* __restrict__ out, int n) {
    int warp = (blockIdx.x * blockDim.x + threadIdx.x) >> 5;
    int lane = threadIdx.x & 31;
    if (warp >= n) return;
    int start = g_rowptr[warp];
    int end = g_rowptr[warp + 1];
    float4 a0 = make_float4(0.f, 0.f, 0.f, 0.f);
    float4 a1 = make_float4(0.f, 0.f, 0.f, 0.f);
    int j = start;
    for (; j + 2 <= end; j += 2) {
        int2 e0 = g_edge[j];
        int2 e1 = g_edge[j + 1];
        float n0 = __int_as_float(e0.y);
        float n1 = __int_as_float(e1.y);
        float4 v0 = __ldg(&h[(size_t)e0.x * 32 + lane]);
        float4 v1 = __ldg(&h[(size_t)e1.x * 32 + lane]);
        a0.x += n0 * v0.x; a0.y += n0 * v0.y; a0.z += n0 * v0.z; a0.w += n0 * v0.w;
        a1.x += n1 * v1.x; a1.y += n1 * v1.y; a1.z += n1 * v1.z; a1.w += n1 * v1.w;
    }
    if (j < end) {
        int2 e0 = g_edge[j];
        float n0 = __int_as_float(e0.y);
        float4 v0 = __ldg(&h[(size_t)e0.x * 32 + lane]);
        a0.x += n0 * v0.x; a0.y += n0 * v0.y; a0.z += n0 * v0.z; a0.w += n0 * v0.w;
    }
    float4 r = make_float4(a0.x + a1.x, a0.y + a1.y, a0.z + a1.z, a0.w + a1.w);
    *(float4*)&out[(size_t)warp * D + lane * 4] = r;
}

extern "C" void kernel_launch(void* const* d_in, const int* in_sizes, int n_in,
                              void* d_out, int out_size) {
    const float* x  = (const float*)d_in[0];
    const int*   ei = (const int*)d_in[1];
    const float* ew = (const float*)d_in[2];
    const float* W1 = (const float*)d_in[3];
    const float* b1 = (const float*)d_in[4];
    const float* W2 = (const float*)d_in[5];
    const float* b2 = (const float*)d_in[6];
    float* out = (float*)d_out;

    int n = in_sizes[0] / D;
    int E = in_sizes[2];
    const int* row = ei;
    const int* col = ei + E;

    void *p_h1, *p_agg1, *p_h2, *p_deg, *p_cnt, *p_cnt2, *p_Wt1, *p_Wt2;
    cudaGetSymbolAddress(&p_h1, g_h1);
    cudaGetSymbolAddress(&p_agg1, g_agg1);
    cudaGetSymbolAddress(&p_h2, g_h2);
    cudaGetSymbolAddress(&p_deg, g_deg);
    cudaGetSymbolAddress(&p_cnt, g_cnt);
    cudaGetSymbolAddress(&p_cnt2, g_cnt2);
    cudaGetSymbolAddress(&p_Wt1, g_Wt1);
    cudaGetSymbolAddress(&p_Wt2, g_Wt2);

    cudaMemsetAsync(p_deg, 0, (size_t)n * sizeof(float));
    cudaMemsetAsync(p_cnt, 0, (size_t)n * sizeof(int));
    cudaMemsetAsync(p_cnt2, 0, (size_t)n * sizeof(int));

    // W transposes (cheap, once)
    transpose_kernel<<<dim3(4, 4), dim3(32, 8)>>>(W1, (float*)p_Wt1);
    transpose_kernel<<<dim3(4, 4), dim3(32, 8)>>>(W2, (float*)p_Wt2);

    // CSR build + normalization
    hist_kernel<<<(E + 255) / 256, 256>>>(ew, row, col, E);
    dis_kernel<<<(n + 255) / 256, 256>>>(n);
    scan_kernel<<<1, 1024>>>(n, E);
    fill_kernel<<<(E + 255) / 256, 256>>>(ew, row, col, E);

    int gemm_blocks = (n + 63) / 64;
    int gather_blocks = (n * 32 + 255) / 256;

    // layer 1
    gemm_kernel<false><<<gemm_blocks, 256>>>(x, (const float*)p_Wt1, b1, (float*)p_h1, n);
    gather_kernel<<<gather_blocks, 256>>>((const float4*)p_h1, (float*)p_agg1, n);

    // layer 2 (relu fused into GEMM input load)
    gemm_kernel<true><<<gemm_blocks, 256>>>((const float*)p_agg1, (const float*)p_Wt2, b2, (float*)p_h2, n);
    gather_kernel<<<gather_blocks, 256>>>((const float4*)p_h2, out, n);
}